// round 5
// baseline (speedup 1.0000x reference)
#include <cuda_runtime.h>
#include <math.h>

#define BATCH   256
#define D_INNER 5120
#define DT_RANK 160
#define NSTATE  16
#define NCOLS   192           // 160 (W_delta) + 16 (W_B) + 16 (W_C)

#define MT   32               // batch tile
#define KC   256              // K chunk for gemm1
#define NKC  (D_INNER / KC)   // 20
#define NMT  (BATCH / MT)     // 8
#define NDT  (D_INNER / 256)  // 20 d-chunks for main kernel

// Scratch (allocation-free rule: __device__ globals)
__device__ float g_part[NKC * BATCH * NCOLS];  // 3.93 MB partials
__device__ float g_T [BATCH * DT_RANK];
__device__ float g_Bp[BATCH * NSTATE];
__device__ float g_C [BATCH * NSTATE];

// ---------------------------------------------------------------------------
// Kernel 1: partial GEMM  P[c] += x[mtile, kchunk] @ [W_delta | W_B | W_C]
// grid (NMT, NKC), block 256. Deterministic (no atomics): each block writes
// its own partial slab.
// ---------------------------------------------------------------------------
__global__ __launch_bounds__(256)
void k_gemm1(const float* __restrict__ x,
             const float* __restrict__ Wd,
             const float* __restrict__ Wb,
             const float* __restrict__ Wc)
{
    __shared__ __align__(16) float xs[MT * KC];   // 32 KB
    const int m0  = blockIdx.x * MT;
    const int k0  = blockIdx.y * KC;
    const int tid = threadIdx.x;

    // Load x tile (coalesced float4)
    for (int i = tid; i < MT * (KC / 4); i += 256) {
        int m  = i / (KC / 4);
        int kq = i % (KC / 4);
        ((float4*)xs)[m * (KC / 4) + kq] =
            *(const float4*)(x + (size_t)(m0 + m) * D_INNER + k0 + kq * 4);
    }
    __syncthreads();

    if (tid < NCOLS) {
        const float* wptr;
        int wstride;
        if (tid < DT_RANK) {
            wptr = Wd + (size_t)k0 * DT_RANK + tid;           wstride = DT_RANK;
        } else if (tid < DT_RANK + NSTATE) {
            wptr = Wb + (size_t)k0 * NSTATE + (tid - DT_RANK); wstride = NSTATE;
        } else {
            wptr = Wc + (size_t)k0 * NSTATE + (tid - DT_RANK - NSTATE); wstride = NSTATE;
        }

        float acc[MT];
        #pragma unroll
        for (int m = 0; m < MT; m++) acc[m] = 0.f;

        #pragma unroll 1
        for (int k = 0; k < KC; k += 4) {
            float w0 = wptr[0];
            float w1 = wptr[wstride];
            float w2 = wptr[2 * wstride];
            float w3 = wptr[3 * wstride];
            wptr += 4 * wstride;
            const float4* xrow = (const float4*)xs + (k >> 2);
            #pragma unroll
            for (int m = 0; m < MT; m++) {
                float4 xv = xrow[m * (KC / 4)];
                float a = acc[m];
                a = fmaf(xv.x, w0, a);
                a = fmaf(xv.y, w1, a);
                a = fmaf(xv.z, w2, a);
                a = fmaf(xv.w, w3, a);
                acc[m] = a;
            }
        }

        float* pout = g_part + ((size_t)blockIdx.y * BATCH + m0) * NCOLS + tid;
        #pragma unroll
        for (int m = 0; m < MT; m++) pout[(size_t)m * NCOLS] = acc[m];
    }
}

// ---------------------------------------------------------------------------
// Kernel 2: reduce the 20 K-chunk partials -> T / Bp / C
// ---------------------------------------------------------------------------
__global__ __launch_bounds__(256)
void k_reduce()
{
    int idx = blockIdx.x * 256 + threadIdx.x;      // 0 .. 49151
    if (idx >= BATCH * NCOLS) return;
    int row = idx / NCOLS;
    int n   = idx % NCOLS;
    float s = 0.f;
    #pragma unroll
    for (int c = 0; c < NKC; c++)
        s += g_part[((size_t)c * BATCH + row) * NCOLS + n];
    if (n < DT_RANK)                  g_T [row * DT_RANK + n] = s;
    else if (n < DT_RANK + NSTATE)    g_Bp[row * NSTATE + (n - DT_RANK)] = s;
    else                              g_C [row * NSTATE + (n - DT_RANK - NSTATE)] = s;
}

// ---------------------------------------------------------------------------
// Kernel 3: fused  dt = softplus(T @ W_dt + b_dt);  SSM step + readout.
// grid (NMT, NDT), block 256 (one thread per d in a 256-wide chunk).
// Each thread computes 32 batches for its d.
// ---------------------------------------------------------------------------
__global__ __launch_bounds__(256)
void k_main(const float* __restrict__ x,
            const float* __restrict__ h,
            const float* __restrict__ Wdt,
            const float* __restrict__ b_dt,
            const float* __restrict__ A_log,
            const float* __restrict__ Dv,
            float* __restrict__ out)
{
    __shared__ __align__(16) float Ts[MT * DT_RANK];   // 20 KB
    __shared__ __align__(16) float Bs[MT * NSTATE];
    __shared__ __align__(16) float Cs[MT * NSTATE];

    const int m0  = blockIdx.x * MT;
    const int tid = threadIdx.x;
    const int d   = blockIdx.y * 256 + tid;

    // Ts tile is contiguous in global T (rows m0..m0+31)
    for (int i = tid; i < MT * DT_RANK; i += 256)
        Ts[i] = g_T[(size_t)m0 * DT_RANK + i];
    for (int i = tid; i < MT * NSTATE; i += 256) {
        Bs[i] = g_Bp[(size_t)m0 * NSTATE + i];
        Cs[i] = g_C [(size_t)m0 * NSTATE + i];
    }
    __syncthreads();

    // A row for this d: A = -exp(A_log)   (reused over 32 batches)
    float a[NSTATE];
    #pragma unroll
    for (int nq = 0; nq < 4; nq++) {
        float4 al = *(const float4*)(A_log + (size_t)d * NSTATE + nq * 4);
        a[nq * 4 + 0] = -__expf(al.x);
        a[nq * 4 + 1] = -__expf(al.y);
        a[nq * 4 + 2] = -__expf(al.z);
        a[nq * 4 + 3] = -__expf(al.w);
    }
    const float bdt = b_dt[d];
    const float Dd  = Dv[d];

    // GEMM2: acc[m] = b_dt[d] + sum_r Ts[m][r] * W_dt[r][d]
    float acc[MT];
    #pragma unroll
    for (int m = 0; m < MT; m++) acc[m] = bdt;

    const float* wp = Wdt + d;
    #pragma unroll 1
    for (int r = 0; r < DT_RANK; r += 4) {
        float w0 = wp[(size_t)(r + 0) * D_INNER];
        float w1 = wp[(size_t)(r + 1) * D_INNER];
        float w2 = wp[(size_t)(r + 2) * D_INNER];
        float w3 = wp[(size_t)(r + 3) * D_INNER];
        #pragma unroll
        for (int m = 0; m < MT; m++) {
            float4 t = *(const float4*)(Ts + m * DT_RANK + r);
            float aa = acc[m];
            aa = fmaf(t.x, w0, aa);
            aa = fmaf(t.y, w1, aa);
            aa = fmaf(t.z, w2, aa);
            aa = fmaf(t.w, w3, aa);
            acc[m] = aa;
        }
    }

    // Epilogue: softplus, abar, h update (virtual), readout
    #pragma unroll 4
    for (int m = 0; m < MT; m++) {
        const int  mg = m0 + m;
        const float z  = acc[m];
        const float dt = (z > 20.f) ? z : log1pf(__expf(z));
        const float xv = x[(size_t)mg * D_INNER + d];
        const float dtx = dt * xv;

        const float4* hp = (const float4*)(h + ((size_t)mg * D_INNER + d) * NSTATE);
        float y = 0.f;
        #pragma unroll
        for (int nq = 0; nq < 4; nq++) {
            float4 h4 = hp[nq];
            const int nb = m * NSTATE + nq * 4;
            float hn;
            hn = fmaf(__expf(dt * a[nq*4+0]), h4.x, dtx * Bs[nb + 0]); y = fmaf(hn, Cs[nb + 0], y);
            hn = fmaf(__expf(dt * a[nq*4+1]), h4.y, dtx * Bs[nb + 1]); y = fmaf(hn, Cs[nb + 1], y);
            hn = fmaf(__expf(dt * a[nq*4+2]), h4.z, dtx * Bs[nb + 2]); y = fmaf(hn, Cs[nb + 2], y);
            hn = fmaf(__expf(dt * a[nq*4+3]), h4.w, dtx * Bs[nb + 3]); y = fmaf(hn, Cs[nb + 3], y);
        }
        out[(size_t)mg * D_INNER + d] = fmaf(xv, Dd, y);
    }
}

// ---------------------------------------------------------------------------
// Inputs (metadata order): x, h, W_delta, W_dt, b_dt, A_log, W_B, W_C, D
// ---------------------------------------------------------------------------
extern "C" void kernel_launch(void* const* d_in, const int* in_sizes, int n_in,
                              void* d_out, int out_size)
{
    const float* x      = (const float*)d_in[0];
    const float* h      = (const float*)d_in[1];
    const float* Wdelta = (const float*)d_in[2];
    const float* Wdt    = (const float*)d_in[3];
    const float* bdt    = (const float*)d_in[4];
    const float* Alog   = (const float*)d_in[5];
    const float* WB     = (const float*)d_in[6];
    const float* WC     = (const float*)d_in[7];
    const float* Dv     = (const float*)d_in[8];
    float* out = (float*)d_out;

    k_gemm1<<<dim3(NMT, NKC), 256>>>(x, Wdelta, WB, WC);
    k_reduce<<<(BATCH * NCOLS + 255) / 256, 256>>>();
    k_main<<<dim3(NMT, NDT), 256>>>(x, h, Wdt, bdt, Alog, Dv, out);
}

// round 6
// speedup vs baseline: 1.2577x; 1.2577x over previous
#include <cuda_runtime.h>
#include <math.h>

#define BATCH   256
#define D_INNER 5120
#define DT_RANK 160
#define NSTATE  16
#define NCOLS   192           // 160 (W_delta) + 16 (W_B) + 16 (W_C)

#define MT    32              // batch tile
#define KC1   128             // K chunk for gemm1
#define NKC   (D_INNER / KC1) // 40
#define NMT   (BATCH / MT)    // 8
#define DT_NT 128             // d-tile for k_dt

// Scratch (allocation-free rule: __device__ globals)
__device__ float g_part[NKC * BATCH * NCOLS];   // 7.86 MB partials
__device__ float g_T  [BATCH * DT_RANK];
__device__ float g_Bp [BATCH * NSTATE];
__device__ float g_C  [BATCH * NSTATE];
__device__ float g_A  [D_INNER * NSTATE];       // -exp(A_log)
__device__ float g_dt [BATCH * D_INNER];        // 5.24 MB softplus output

// ---------------------------------------------------------------------------
// Kernel 1: partial GEMM  P[c] = x[mtile, kchunk] @ [W_delta | W_B | W_C]
// grid (8, 40), block 192 (one thread per output column). Prefetched W quad.
// ---------------------------------------------------------------------------
__global__ __launch_bounds__(192)
void k_gemm1(const float* __restrict__ x,
             const float* __restrict__ Wd,
             const float* __restrict__ Wb,
             const float* __restrict__ Wc)
{
    __shared__ __align__(16) float xs[MT * KC1];   // 16 KB
    const int m0  = blockIdx.x * MT;
    const int k0  = blockIdx.y * KC1;
    const int tid = threadIdx.x;

    for (int i = tid; i < MT * (KC1 / 4); i += 192)
        ((float4*)xs)[i] =
            *(const float4*)(x + (size_t)(m0 + i / (KC1 / 4)) * D_INNER
                               + k0 + (i % (KC1 / 4)) * 4);
    __syncthreads();

    const float* wptr;
    int wstride;
    if (tid < DT_RANK) {
        wptr = Wd + (size_t)k0 * DT_RANK + tid;                wstride = DT_RANK;
    } else if (tid < DT_RANK + NSTATE) {
        wptr = Wb + (size_t)k0 * NSTATE + (tid - DT_RANK);     wstride = NSTATE;
    } else {
        wptr = Wc + (size_t)k0 * NSTATE + (tid - DT_RANK - NSTATE); wstride = NSTATE;
    }

    float acc[MT];
    #pragma unroll
    for (int m = 0; m < MT; m++) acc[m] = 0.f;

    // software-pipelined W quad
    float w0 = wptr[0], w1 = wptr[wstride], w2 = wptr[2 * wstride], w3 = wptr[3 * wstride];

    #pragma unroll 2
    for (int k = 0; k < KC1; k += 4) {
        const float* wn = wptr + 4 * wstride;
        float n0 = w0, n1 = w1, n2 = w2, n3 = w3;
        if (k + 4 < KC1) {
            n0 = wn[0]; n1 = wn[wstride]; n2 = wn[2 * wstride]; n3 = wn[3 * wstride];
        }
        const float4* xrow = (const float4*)xs + (k >> 2);
        #pragma unroll
        for (int m = 0; m < MT; m++) {
            float4 xv = xrow[m * (KC1 / 4)];
            float a = acc[m];
            a = fmaf(xv.x, w0, a);
            a = fmaf(xv.y, w1, a);
            a = fmaf(xv.z, w2, a);
            a = fmaf(xv.w, w3, a);
            acc[m] = a;
        }
        w0 = n0; w1 = n1; w2 = n2; w3 = n3; wptr = wn;
    }

    float* pout = g_part + ((size_t)blockIdx.y * BATCH + m0) * NCOLS + tid;
    #pragma unroll
    for (int m = 0; m < MT; m++) pout[(size_t)m * NCOLS] = acc[m];
}

// ---------------------------------------------------------------------------
// Kernel 2: reduce 40 K-chunk partials -> T / Bp / C
// ---------------------------------------------------------------------------
__global__ __launch_bounds__(256)
void k_reduce()
{
    int idx = blockIdx.x * 256 + threadIdx.x;
    if (idx >= BATCH * NCOLS) return;
    int row = idx / NCOLS;
    int n   = idx % NCOLS;
    float s = 0.f;
    #pragma unroll
    for (int c = 0; c < NKC; c++)
        s += g_part[((size_t)c * BATCH + row) * NCOLS + n];
    if (n < DT_RANK)               g_T [row * DT_RANK + n] = s;
    else if (n < DT_RANK + NSTATE) g_Bp[row * NSTATE + (n - DT_RANK)] = s;
    else                           g_C [row * NSTATE + (n - DT_RANK - NSTATE)] = s;
}

// ---------------------------------------------------------------------------
// Kernel 3: A = -exp(A_log)   (tiny, 82K elements)
// ---------------------------------------------------------------------------
__global__ __launch_bounds__(256)
void k_prep(const float* __restrict__ A_log)
{
    int idx = blockIdx.x * 256 + threadIdx.x;
    if (idx < D_INNER * NSTATE) g_A[idx] = -__expf(A_log[idx]);
}

// ---------------------------------------------------------------------------
// Kernel 4: dt = softplus(T @ W_dt + b_dt)
// Register-tiled GEMM: M=256, N=5120, K=160. grid (8, 40), block 256,
// 4x4 outputs per thread. T tile fully resident in smem; W_dt streamed
// through smem in 32-row chunks.
// ---------------------------------------------------------------------------
__global__ __launch_bounds__(256)
void k_dt(const float* __restrict__ Wdt, const float* __restrict__ b_dt)
{
    __shared__ __align__(16) float Ts[MT * DT_RANK];   // 20 KB
    __shared__ __align__(16) float ws[32 * DT_NT];     // 16 KB
    const int m0  = blockIdx.x * MT;
    const int d0  = blockIdx.y * DT_NT;
    const int tid = threadIdx.x;
    const int mg  = tid >> 5;   // 0..7  -> m rows mg*4 .. mg*4+3
    const int ng  = tid & 31;   // 0..31 -> d cols ng*4 .. ng*4+3

    for (int i = tid; i < MT * DT_RANK / 4; i += 256)
        ((float4*)Ts)[i] = ((const float4*)(g_T + (size_t)m0 * DT_RANK))[i];

    float acc[4][4];
    #pragma unroll
    for (int a = 0; a < 4; a++)
        #pragma unroll
        for (int b = 0; b < 4; b++) acc[a][b] = 0.f;

    for (int kc = 0; kc < DT_RANK; kc += 32) {
        __syncthreads();
        for (int i = tid; i < 32 * (DT_NT / 4); i += 256)
            ((float4*)ws)[i] =
                *(const float4*)(Wdt + (size_t)(kc + i / (DT_NT / 4)) * D_INNER
                                     + d0 + (i % (DT_NT / 4)) * 4);
        __syncthreads();

        #pragma unroll
        for (int k = 0; k < 32; k++) {
            float4 wv = ((const float4*)ws)[k * (DT_NT / 4) + ng];
            float t0 = Ts[(mg * 4 + 0) * DT_RANK + kc + k];
            float t1 = Ts[(mg * 4 + 1) * DT_RANK + kc + k];
            float t2 = Ts[(mg * 4 + 2) * DT_RANK + kc + k];
            float t3 = Ts[(mg * 4 + 3) * DT_RANK + kc + k];
            acc[0][0] = fmaf(t0, wv.x, acc[0][0]);
            acc[0][1] = fmaf(t0, wv.y, acc[0][1]);
            acc[0][2] = fmaf(t0, wv.z, acc[0][2]);
            acc[0][3] = fmaf(t0, wv.w, acc[0][3]);
            acc[1][0] = fmaf(t1, wv.x, acc[1][0]);
            acc[1][1] = fmaf(t1, wv.y, acc[1][1]);
            acc[1][2] = fmaf(t1, wv.z, acc[1][2]);
            acc[1][3] = fmaf(t1, wv.w, acc[1][3]);
            acc[2][0] = fmaf(t2, wv.x, acc[2][0]);
            acc[2][1] = fmaf(t2, wv.y, acc[2][1]);
            acc[2][2] = fmaf(t2, wv.z, acc[2][2]);
            acc[2][3] = fmaf(t2, wv.w, acc[2][3]);
            acc[3][0] = fmaf(t3, wv.x, acc[3][0]);
            acc[3][1] = fmaf(t3, wv.y, acc[3][1]);
            acc[3][2] = fmaf(t3, wv.z, acc[3][2]);
            acc[3][3] = fmaf(t3, wv.w, acc[3][3]);
        }
    }

    const float4 bd = *(const float4*)(b_dt + d0 + ng * 4);
    #pragma unroll
    for (int a = 0; a < 4; a++) {
        const int m = m0 + mg * 4 + a;
        float4 z;
        z.x = acc[a][0] + bd.x;
        z.y = acc[a][1] + bd.y;
        z.z = acc[a][2] + bd.z;
        z.w = acc[a][3] + bd.w;
        z.x = (z.x > 20.f) ? z.x : log1pf(__expf(z.x));
        z.y = (z.y > 20.f) ? z.y : log1pf(__expf(z.y));
        z.z = (z.z > 20.f) ? z.z : log1pf(__expf(z.z));
        z.w = (z.w > 20.f) ? z.w : log1pf(__expf(z.w));
        *(float4*)(g_dt + (size_t)m * D_INNER + d0 + ng * 4) = z;
    }
}

// ---------------------------------------------------------------------------
// Kernel 5: streaming epilogue. grid (8, 160), block 256.
// Block tile: 32 batches x 32 d. Thread: fixed d, 4 batches (A row reused).
// ---------------------------------------------------------------------------
__global__ __launch_bounds__(256)
void k_epi(const float* __restrict__ x,
           const float* __restrict__ h,
           const float* __restrict__ Dv,
           float* __restrict__ out)
{
    __shared__ float Bsh[32 * NSTATE];
    __shared__ float Csh[32 * NSTATE];
    const int b0  = blockIdx.x * 32;
    const int d0  = blockIdx.y * 32;
    const int tid = threadIdx.x;
    const int dl  = tid & 31;          // d lane
    const int bg  = tid >> 5;          // batch group 0..7 (4 batches each)

    for (int i = tid; i < 32 * NSTATE; i += 256) {
        Bsh[i] = g_Bp[b0 * NSTATE + i];
        Csh[i] = g_C [b0 * NSTATE + i];
    }
    __syncthreads();

    const int d = d0 + dl;
    float a[NSTATE];
    #pragma unroll
    for (int q = 0; q < 4; q++) {
        float4 av = *(const float4*)(g_A + (size_t)d * NSTATE + q * 4);
        a[q * 4 + 0] = av.x; a[q * 4 + 1] = av.y;
        a[q * 4 + 2] = av.z; a[q * 4 + 3] = av.w;
    }
    const float Dd = Dv[d];

    #pragma unroll
    for (int i = 0; i < 4; i++) {
        const int b = b0 + bg * 4 + i;
        const size_t off = (size_t)b * D_INNER + d;
        const float dt  = g_dt[off];
        const float xv  = x[off];
        const float dtx = dt * xv;
        const float4* hp = (const float4*)(h + off * NSTATE);
        const int bb = (bg * 4 + i) * NSTATE;
        float y = 0.f;
        #pragma unroll
        for (int q = 0; q < 4; q++) {
            float4 h4 = hp[q];
            float hn;
            hn = fmaf(__expf(dt * a[q*4+0]), h4.x, dtx * Bsh[bb + q*4+0]); y = fmaf(hn, Csh[bb + q*4+0], y);
            hn = fmaf(__expf(dt * a[q*4+1]), h4.y, dtx * Bsh[bb + q*4+1]); y = fmaf(hn, Csh[bb + q*4+1], y);
            hn = fmaf(__expf(dt * a[q*4+2]), h4.z, dtx * Bsh[bb + q*4+2]); y = fmaf(hn, Csh[bb + q*4+2], y);
            hn = fmaf(__expf(dt * a[q*4+3]), h4.w, dtx * Bsh[bb + q*4+3]); y = fmaf(hn, Csh[bb + q*4+3], y);
        }
        out[off] = fmaf(xv, Dd, y);
    }
}

// ---------------------------------------------------------------------------
// Inputs (metadata order): x, h, W_delta, W_dt, b_dt, A_log, W_B, W_C, D
// ---------------------------------------------------------------------------
extern "C" void kernel_launch(void* const* d_in, const int* in_sizes, int n_in,
                              void* d_out, int out_size)
{
    const float* x      = (const float*)d_in[0];
    const float* h      = (const float*)d_in[1];
    const float* Wdelta = (const float*)d_in[2];
    const float* Wdt    = (const float*)d_in[3];
    const float* bdt    = (const float*)d_in[4];
    const float* Alog   = (const float*)d_in[5];
    const float* WB     = (const float*)d_in[6];
    const float* WC     = (const float*)d_in[7];
    const float* Dv     = (const float*)d_in[8];
    float* out = (float*)d_out;

    k_gemm1<<<dim3(NMT, NKC), 192>>>(x, Wdelta, WB, WC);
    k_prep<<<(D_INNER * NSTATE + 255) / 256, 256>>>(Alog);
    k_reduce<<<(BATCH * NCOLS + 255) / 256, 256>>>();
    k_dt<<<dim3(NMT, D_INNER / DT_NT), 256>>>(Wdt, bdt);
    k_epi<<<dim3(BATCH / 32, D_INNER / 32), 256>>>(x, h, Dv, out);
}